// round 6
// baseline (speedup 1.0000x reference)
#include <cuda_runtime.h>
#include <math.h>

typedef unsigned long long u64;
typedef ulonglong2 u64x2;

#define Hn   256
#define Wn   256
#define CIN  64
#define COUT 64
#define Bn   16

__device__ __forceinline__ u64 f2u(float lo, float hi) {
    u64 r; asm("mov.b64 %0, {%1,%2};" : "=l"(r) : "f"(lo), "f"(hi)); return r;
}
__device__ __forceinline__ float2 u2f(u64 v) {
    float2 r; asm("mov.b64 {%0,%1}, %2;" : "=f"(r.x), "=f"(r.y) : "l"(v)); return r;
}
__device__ __forceinline__ u64 ffma2(u64 a, u64 b, u64 c) {
    u64 d; asm("fma.rn.f32x2 %0, %1, %2, %3;" : "=l"(d) : "l"(a), "l"(b), "l"(c));
    return d;
}

// Intermediate spectra, packed (re, im) in one u64
__device__ u64 g_X[Bn * CIN * 1024];
__device__ u64 g_S[Bn * COUT * 1024];

// ---------------------------------------------------------------------------
// Forward: per (b,i) block, 256x256 real -> 32x32 complex modes
// smem: cs[129][32] f2 (cos,-sin) | t4[256] f4 (c,c,s,s) | xeo[32][130] f2 | D[32][32] u64
// ---------------------------------------------------------------------------
#define FWD_SMEM_BYTES (129*32*8 + 256*16 + 32*130*8 + 32*32*8)

__global__ __launch_bounds__(256, 2) void fwd_kernel(const float* __restrict__ x) {
    extern __shared__ char smraw[];
    float2* s_cs  = (float2*)smraw;                 // [w*32 + kx]
    float4* s_t4  = (float4*)(s_cs + 129 * 32);     // [n]
    float2* s_xeo = (float2*)(s_t4 + 256);          // [r*130 + w]
    u64*    s_D   = (u64*)(s_xeo + 32 * 130);       // [r*32 + kx]

    const int t  = threadIdx.x;
    const int bi = blockIdx.x;
    const float* xp = x + (size_t)bi * (Hn * Wn);

    for (int idx = t; idx < 129 * 32; idx += 256) {
        int w = idx >> 5, kx = idx & 31;
        float sv, cv;
        sincospif(((w * kx) & 255) * (2.0f / 256.0f), &sv, &cv);
        s_cs[idx] = make_float2(cv, -sv);
    }
    {
        int n = t;
        float sv, cv;
        sincospif(n * (2.0f / 256.0f), &sv, &cv);
        s_t4[n] = make_float4(cv, cv, sv, sv);
    }

    // warp tile: 8 rows x 16 kx ; thread tile 2x2
    const int warp = t >> 5, lane = t & 31;
    const int kxg  = warp & 1;        // kx half
    const int rg   = warp >> 1;       // row group (0..3)
    const int kl   = lane & 7;
    const int rl   = lane >> 3;
    const int kx0  = kxg * 16 + kl * 2;      // even
    const int row0 = rg * 8 + rl * 2;        // rows row0, row0+1 within chunk

    u64 X[2][2];   // [ky off][kx off], ky0 = row0 mapping reused
    X[0][0] = X[0][1] = X[1][0] = X[1][1] = 0ull;

    const u64* cs64 = (const u64*)s_cs;

    __syncthreads();

    for (int c = 0; c < 8; ++c) {
        const int h0 = c * 32;

        // fold rows
        for (int idx = t; idx < 32 * 129; idx += 256) {
            int r = idx / 129;
            int w = idx - r * 129;
            const float* row = xp + (size_t)(h0 + r) * Wn;
            float a = row[w];
            float b = row[(256 - w) & 255];
            s_xeo[r * 130 + w] = (w == 0 || w == 128) ? make_float2(a, 0.f)
                                                      : make_float2(a + b, a - b);
        }
        __syncthreads();

        // stage 1: folded row DFT  D[r,kx] = (Sum xe*cos, Sum xo*(-sin))
        {
            u64 acc[2][2];
            acc[0][0] = acc[0][1] = acc[1][0] = acc[1][1] = 0ull;
            #pragma unroll 4
            for (int w = 0; w < 128; w += 2) {
                u64x2 csA = *(const u64x2*)&cs64[w * 32 + kx0];        // kx0,kx0+1 @ w
                u64x2 csB = *(const u64x2*)&cs64[(w + 1) * 32 + kx0];  // @ w+1
                u64x2 v0  = *(const u64x2*)&s_xeo[row0 * 130 + w];
                u64x2 v1  = *(const u64x2*)&s_xeo[(row0 + 1) * 130 + w];
                acc[0][0] = ffma2(v0.x, csA.x, acc[0][0]);
                acc[0][0] = ffma2(v0.y, csB.x, acc[0][0]);
                acc[0][1] = ffma2(v0.x, csA.y, acc[0][1]);
                acc[0][1] = ffma2(v0.y, csB.y, acc[0][1]);
                acc[1][0] = ffma2(v1.x, csA.x, acc[1][0]);
                acc[1][0] = ffma2(v1.y, csB.x, acc[1][0]);
                acc[1][1] = ffma2(v1.x, csA.y, acc[1][1]);
                acc[1][1] = ffma2(v1.y, csB.y, acc[1][1]);
            }
            {   // w = 128 tail (xo = 0 there)
                u64x2 csA = *(const u64x2*)&cs64[128 * 32 + kx0];
                u64 v0 = *(const u64*)&s_xeo[row0 * 130 + 128];
                u64 v1 = *(const u64*)&s_xeo[(row0 + 1) * 130 + 128];
                acc[0][0] = ffma2(v0, csA.x, acc[0][0]);
                acc[0][1] = ffma2(v0, csA.y, acc[0][1]);
                acc[1][0] = ffma2(v1, csA.x, acc[1][0]);
                acc[1][1] = ffma2(v1, csA.y, acc[1][1]);
            }
            s_D[row0 * 32 + kx0]           = acc[0][0];
            s_D[row0 * 32 + kx0 + 1]       = acc[0][1];
            s_D[(row0 + 1) * 32 + kx0]     = acc[1][0];
            s_D[(row0 + 1) * 32 + kx0 + 1] = acc[1][1];
        }
        __syncthreads();

        // stage 2: accumulate over h.  ky tile = row tile mapping (row0 -> ky0)
        #pragma unroll 4
        for (int r = 0; r < 32; ++r) {
            const int h = h0 + r;
            u64x2 dp = *(const u64x2*)&s_D[r * 32 + kx0];
            float2 d0 = u2f(dp.x), d1 = u2f(dp.y);
            u64 dq0 = f2u(d0.y, -d0.x);
            u64 dq1 = f2u(d1.y, -d1.x);
            u64x2 e0 = *(const u64x2*)&s_t4[(row0 * h) & 255];
            u64x2 e1 = *(const u64x2*)&s_t4[((row0 + 1) * h) & 255];
            X[0][0] = ffma2(dp.x, e0.x, X[0][0]);
            X[0][0] = ffma2(dq0,  e0.y, X[0][0]);
            X[0][1] = ffma2(dp.y, e0.x, X[0][1]);
            X[0][1] = ffma2(dq1,  e0.y, X[0][1]);
            X[1][0] = ffma2(dp.x, e1.x, X[1][0]);
            X[1][0] = ffma2(dq0,  e1.y, X[1][0]);
            X[1][1] = ffma2(dp.y, e1.x, X[1][1]);
            X[1][1] = ffma2(dq1,  e1.y, X[1][1]);
        }
        __syncthreads();
    }

    #pragma unroll
    for (int j = 0; j < 2; ++j)
        #pragma unroll
        for (int i = 0; i < 2; ++i)
            g_X[(size_t)bi * 1024 + (row0 + j) * 32 + kx0 + i] = X[j][i];
}

// ---------------------------------------------------------------------------
// Mix: per mode m: S[b,o] = sum_i X[b,i] * W[i,o]   (packed complex * real)
// ---------------------------------------------------------------------------
__global__ __launch_bounds__(256) void mix_kernel(const float* __restrict__ wts) {
    __shared__ float s_W[CIN * COUT];
    __shared__ u64   s_X[Bn * CIN];
    const int t = threadIdx.x;
    const int m = blockIdx.x;

    for (int e = t; e < CIN * COUT; e += 256)
        s_W[e] = wts[(size_t)e * 1024 + m];
    for (int e = t; e < Bn * CIN; e += 256)
        s_X[e] = g_X[(size_t)e * 1024 + m];
    __syncthreads();

    const int o  = t & 63;
    const int bq = t >> 6;
    u64 acc[4] = {0ull, 0ull, 0ull, 0ull};

    #pragma unroll 8
    for (int i = 0; i < CIN; ++i) {
        float wv = s_W[i * 64 + o];
        u64 wp = f2u(wv, wv);
        #pragma unroll
        for (int j = 0; j < 4; ++j)
            acc[j] = ffma2(s_X[(bq * 4 + j) * 64 + i], wp, acc[j]);
    }
    #pragma unroll
    for (int j = 0; j < 4; ++j)
        g_S[((size_t)(bq * 4 + j) * 64 + o) * 1024 + m] = acc[j];
}

// ---------------------------------------------------------------------------
// Inverse: per (b,o) block, 32x32 modes -> 256x256 real + bias
// smem: ci[32][130] f2 (c,s) | t4i[256] f4 (c,s,-s,c) | S[32][32] u64 | G[16][32] u64
// ---------------------------------------------------------------------------
#define INV_SMEM_BYTES (32*130*8 + 256*16 + 32*32*8 + 16*32*8)

__global__ __launch_bounds__(256) void inv_kernel(const float* __restrict__ bias,
                                                  float* __restrict__ out) {
    extern __shared__ char smraw[];
    float2* s_ci  = (float2*)smraw;                 // [kk*130 + w]
    float4* s_t4i = (float4*)(s_ci + 32 * 130);     // [n] = (c, s, -s, c)
    u64*    s_S   = (u64*)(s_t4i + 256);            // [ky*32 + kx], pre-scaled
    u64*    s_G   = s_S + 32 * 32;                  // [r*32 + kk]

    const int t  = threadIdx.x;
    const int bo = blockIdx.x;
    const int o  = bo & 63;

    for (int idx = t; idx < 32 * 129; idx += 256) {
        int kk = idx / 129;
        int w  = idx - kk * 129;
        float sv, cv;
        sincospif(((kk * w) & 255) * (2.0f / 256.0f), &sv, &cv);
        s_ci[kk * 130 + w] = make_float2(cv, sv);
    }
    {
        int n = t;
        float sv, cv;
        sincospif(n * (2.0f / 256.0f), &sv, &cv);
        s_t4i[n] = make_float4(cv, sv, -sv, cv);
    }
    for (int e = t; e < 1024; e += 256) {
        float2 v  = u2f(g_S[(size_t)bo * 1024 + e]);
        float sc  = ((e & 31) == 0 ? 1.f : 2.f) * (1.f / 65536.f);
        s_S[e] = f2u(v.x * sc, v.y * sc);
    }
    const float bias_o = bias[o];
    __syncthreads();

    // C1 mapping: lanes over kx, warp -> row pair
    const int kx = t & 31, r2 = t >> 5;
    // C2 mapping: warp tile = 16 w x 16 rows; thread 2 w x 4 rows
    const int warp = t >> 5, lane = t & 31;
    const int wl = lane & 7, rl = lane >> 3;
    const int w0 = warp * 16 + wl * 2;           // even, 0..126

    const u64* ci64 = (const u64*)s_ci;
    float* yp = out + (size_t)bo * (Hn * Wn);

    for (int c = 0; c < 16; ++c) {
        const int hb = c * 16;

        // ---- C1: G[h,kx] = sum_ky S * e^{+2 pi i ky h/256}
        {
            const int h1 = hb + r2, h2 = h1 + 8;
            u64 a1 = 0ull, a2 = 0ull;
            #pragma unroll 8
            for (int ky = 0; ky < 32; ++ky) {
                float2 sv = u2f(s_S[ky * 32 + kx]);
                u64 sxx = f2u(sv.x, sv.x);
                u64 syy = f2u(sv.y, sv.y);
                u64x2 e1 = *(const u64x2*)&s_t4i[(ky * h1) & 255];
                u64x2 e2 = *(const u64x2*)&s_t4i[(ky * h2) & 255];
                a1 = ffma2(sxx, e1.x, a1);
                a1 = ffma2(syy, e1.y, a1);
                a2 = ffma2(sxx, e2.x, a2);
                a2 = ffma2(syy, e2.y, a2);
            }
            s_G[r2 * 32 + kx]       = a1;
            s_G[(r2 + 8) * 32 + kx] = a2;
        }
        __syncthreads();

        // ---- C2: y over (16 rows x cols w0,w0+1 and mirrors)
        {
            u64 acc[4][2];
            float aN[4];
            #pragma unroll
            for (int u = 0; u < 4; ++u) {
                acc[u][0] = acc[u][1] = 0ull; aN[u] = 0.f;
            }
            #pragma unroll 4
            for (int kk = 0; kk < 32; kk += 2) {
                u64x2 cs0 = *(const u64x2*)&ci64[kk * 130 + w0];        // (c,s) @ (kk, w0/w0+1)
                u64x2 cs1 = *(const u64x2*)&ci64[(kk + 1) * 130 + w0];
                #pragma unroll
                for (int u = 0; u < 4; ++u) {
                    u64x2 gv = *(const u64x2*)&s_G[(u * 4 + rl) * 32 + kk];
                    acc[u][0] = ffma2(gv.x, cs0.x, acc[u][0]);
                    acc[u][0] = ffma2(gv.y, cs1.x, acc[u][0]);
                    acc[u][1] = ffma2(gv.x, cs0.y, acc[u][1]);
                    acc[u][1] = ffma2(gv.y, cs1.y, acc[u][1]);
                    if (w0 == 0) {
                        aN[u] += u2f(gv.x).x - u2f(gv.y).x;
                    }
                }
            }
            #pragma unroll
            for (int u = 0; u < 4; ++u) {
                const int h = hb + u * 4 + rl;
                float2 a0 = u2f(acc[u][0]);   // (Sum gR c, Sum gI s) @ w0
                float2 a1 = u2f(acc[u][1]);   // @ w0+1
                float y00 = a0.x - a0.y + bias_o;   // col w0
                float y01 = a1.x - a1.y + bias_o;   // col w0+1
                float y10 = a0.x + a0.y + bias_o;   // col 256-w0
                float y11 = a1.x + a1.y + bias_o;   // col 255-w0
                *(float2*)&yp[h * 256 + w0] = make_float2(y00, y01);
                if (w0 == 0) {
                    yp[h * 256 + 255] = y11;
                    yp[h * 256 + 128] = aN[u] + bias_o;
                } else {
                    yp[h * 256 + (255 - w0)] = y11;
                    yp[h * 256 + (256 - w0)] = y10;
                }
            }
        }
        __syncthreads();
    }
}

// ---------------------------------------------------------------------------
extern "C" void kernel_launch(void* const* d_in, const int* in_sizes, int n_in,
                              void* d_out, int out_size) {
    const float* x    = (const float*)d_in[0];
    const float* wts  = (const float*)d_in[1];
    const float* bias = (const float*)d_in[2];
    float* out = (float*)d_out;

    cudaFuncSetAttribute(fwd_kernel, cudaFuncAttributeMaxDynamicSharedMemorySize,
                         FWD_SMEM_BYTES);
    cudaFuncSetAttribute(inv_kernel, cudaFuncAttributeMaxDynamicSharedMemorySize,
                         INV_SMEM_BYTES);

    fwd_kernel<<<Bn * CIN, 256, FWD_SMEM_BYTES>>>(x);
    mix_kernel<<<1024, 256>>>(wts);
    inv_kernel<<<Bn * COUT, 256, INV_SMEM_BYTES>>>(bias, out);
}

// round 7
// speedup vs baseline: 1.0030x; 1.0030x over previous
#include <cuda_runtime.h>
#include <math.h>

typedef unsigned long long u64;
typedef ulonglong2 u64x2;

#define Hn   256
#define Wn   256
#define CIN  64
#define COUT 64
#define Bn   16

__device__ __forceinline__ u64 f2u(float lo, float hi) {
    u64 r; asm("mov.b64 %0, {%1,%2};" : "=l"(r) : "f"(lo), "f"(hi)); return r;
}
__device__ __forceinline__ float2 u2f(u64 v) {
    float2 r; asm("mov.b64 {%0,%1}, %2;" : "=f"(r.x), "=f"(r.y) : "l"(v)); return r;
}
__device__ __forceinline__ u64 ffma2(u64 a, u64 b, u64 c) {
    u64 d; asm("fma.rn.f32x2 %0, %1, %2, %3;" : "=l"(d) : "l"(a), "l"(b), "l"(c));
    return d;
}

// Intermediate spectra, packed (re, im) in one u64
__device__ u64 g_X[Bn * CIN * 1024];
__device__ u64 g_S[Bn * COUT * 1024];

// ---------------------------------------------------------------------------
// Forward: per (b,i) block, 256x256 real -> 32x32 complex modes
// smem: cs[129][32] f2 (cos,-sin) | t4[256] f4 (c,c,s,s) | xeo[32][130] f2 | D[32][32] u64
// ---------------------------------------------------------------------------
#define FWD_SMEM_BYTES (129*32*8 + 256*16 + 32*130*8 + 32*32*8)

__global__ __launch_bounds__(256, 2) void fwd_kernel(const float* __restrict__ x) {
    extern __shared__ char smraw[];
    float2* s_cs  = (float2*)smraw;                 // [w*32 + kx]
    float4* s_t4  = (float4*)(s_cs + 129 * 32);     // [n]
    float2* s_xeo = (float2*)(s_t4 + 256);          // [r*130 + w]
    u64*    s_D   = (u64*)(s_xeo + 32 * 130);       // [r*32 + kx]

    const int t  = threadIdx.x;
    const int bi = blockIdx.x;
    const float* xp = x + (size_t)bi * (Hn * Wn);

    for (int idx = t; idx < 129 * 32; idx += 256) {
        int w = idx >> 5, kx = idx & 31;
        float sv, cv;
        sincospif(((w * kx) & 255) * (2.0f / 256.0f), &sv, &cv);
        s_cs[idx] = make_float2(cv, -sv);
    }
    {
        int n = t;
        float sv, cv;
        sincospif(n * (2.0f / 256.0f), &sv, &cv);
        s_t4[n] = make_float4(cv, cv, sv, sv);
    }

    // warp tile: 8 rows x 16 kx ; thread tile 2x2
    const int warp = t >> 5, lane = t & 31;
    const int kxg  = warp & 1;        // kx half
    const int rg   = warp >> 1;       // row group (0..3)
    const int kl   = lane & 7;
    const int rl   = lane >> 3;
    const int kx0  = kxg * 16 + kl * 2;      // even
    const int row0 = rg * 8 + rl * 2;        // rows row0, row0+1 within chunk

    u64 X[2][2];   // [ky off][kx off], ky0 = row0 mapping reused
    X[0][0] = X[0][1] = X[1][0] = X[1][1] = 0ull;

    const u64* cs64 = (const u64*)s_cs;

    __syncthreads();

    for (int c = 0; c < 8; ++c) {
        const int h0 = c * 32;

        // fold rows
        for (int idx = t; idx < 32 * 129; idx += 256) {
            int r = idx / 129;
            int w = idx - r * 129;
            const float* row = xp + (size_t)(h0 + r) * Wn;
            float a = row[w];
            float b = row[(256 - w) & 255];
            s_xeo[r * 130 + w] = (w == 0 || w == 128) ? make_float2(a, 0.f)
                                                      : make_float2(a + b, a - b);
        }
        __syncthreads();

        // stage 1: folded row DFT  D[r,kx] = (Sum xe*cos, Sum xo*(-sin))
        {
            u64 acc[2][2];
            acc[0][0] = acc[0][1] = acc[1][0] = acc[1][1] = 0ull;
            #pragma unroll 4
            for (int w = 0; w < 128; w += 2) {
                u64x2 csA = *(const u64x2*)&cs64[w * 32 + kx0];        // kx0,kx0+1 @ w
                u64x2 csB = *(const u64x2*)&cs64[(w + 1) * 32 + kx0];  // @ w+1
                u64x2 v0  = *(const u64x2*)&s_xeo[row0 * 130 + w];
                u64x2 v1  = *(const u64x2*)&s_xeo[(row0 + 1) * 130 + w];
                acc[0][0] = ffma2(v0.x, csA.x, acc[0][0]);
                acc[0][0] = ffma2(v0.y, csB.x, acc[0][0]);
                acc[0][1] = ffma2(v0.x, csA.y, acc[0][1]);
                acc[0][1] = ffma2(v0.y, csB.y, acc[0][1]);
                acc[1][0] = ffma2(v1.x, csA.x, acc[1][0]);
                acc[1][0] = ffma2(v1.y, csB.x, acc[1][0]);
                acc[1][1] = ffma2(v1.x, csA.y, acc[1][1]);
                acc[1][1] = ffma2(v1.y, csB.y, acc[1][1]);
            }
            {   // w = 128 tail (xo = 0 there)
                u64x2 csA = *(const u64x2*)&cs64[128 * 32 + kx0];
                u64 v0 = *(const u64*)&s_xeo[row0 * 130 + 128];
                u64 v1 = *(const u64*)&s_xeo[(row0 + 1) * 130 + 128];
                acc[0][0] = ffma2(v0, csA.x, acc[0][0]);
                acc[0][1] = ffma2(v0, csA.y, acc[0][1]);
                acc[1][0] = ffma2(v1, csA.x, acc[1][0]);
                acc[1][1] = ffma2(v1, csA.y, acc[1][1]);
            }
            s_D[row0 * 32 + kx0]           = acc[0][0];
            s_D[row0 * 32 + kx0 + 1]       = acc[0][1];
            s_D[(row0 + 1) * 32 + kx0]     = acc[1][0];
            s_D[(row0 + 1) * 32 + kx0 + 1] = acc[1][1];
        }
        __syncthreads();

        // stage 2: accumulate over h.  ky tile = row tile mapping (row0 -> ky0)
        #pragma unroll 4
        for (int r = 0; r < 32; ++r) {
            const int h = h0 + r;
            u64x2 dp = *(const u64x2*)&s_D[r * 32 + kx0];
            float2 d0 = u2f(dp.x), d1 = u2f(dp.y);
            u64 dq0 = f2u(d0.y, -d0.x);
            u64 dq1 = f2u(d1.y, -d1.x);
            u64x2 e0 = *(const u64x2*)&s_t4[(row0 * h) & 255];
            u64x2 e1 = *(const u64x2*)&s_t4[((row0 + 1) * h) & 255];
            X[0][0] = ffma2(dp.x, e0.x, X[0][0]);
            X[0][0] = ffma2(dq0,  e0.y, X[0][0]);
            X[0][1] = ffma2(dp.y, e0.x, X[0][1]);
            X[0][1] = ffma2(dq1,  e0.y, X[0][1]);
            X[1][0] = ffma2(dp.x, e1.x, X[1][0]);
            X[1][0] = ffma2(dq0,  e1.y, X[1][0]);
            X[1][1] = ffma2(dp.y, e1.x, X[1][1]);
            X[1][1] = ffma2(dq1,  e1.y, X[1][1]);
        }
        __syncthreads();
    }

    #pragma unroll
    for (int j = 0; j < 2; ++j)
        #pragma unroll
        for (int i = 0; i < 2; ++i)
            g_X[(size_t)bi * 1024 + (row0 + j) * 32 + kx0 + i] = X[j][i];
}

// ---------------------------------------------------------------------------
// Mix: per mode m: S[b,o] = sum_i X[b,i] * W[i,o]   (packed complex * real)
// ---------------------------------------------------------------------------
__global__ __launch_bounds__(256) void mix_kernel(const float* __restrict__ wts) {
    __shared__ float s_W[CIN * COUT];
    __shared__ u64   s_X[Bn * CIN];
    const int t = threadIdx.x;
    const int m = blockIdx.x;

    for (int e = t; e < CIN * COUT; e += 256)
        s_W[e] = wts[(size_t)e * 1024 + m];
    for (int e = t; e < Bn * CIN; e += 256)
        s_X[e] = g_X[(size_t)e * 1024 + m];
    __syncthreads();

    const int o  = t & 63;
    const int bq = t >> 6;
    u64 acc[4] = {0ull, 0ull, 0ull, 0ull};

    #pragma unroll 8
    for (int i = 0; i < CIN; ++i) {
        float wv = s_W[i * 64 + o];
        u64 wp = f2u(wv, wv);
        #pragma unroll
        for (int j = 0; j < 4; ++j)
            acc[j] = ffma2(s_X[(bq * 4 + j) * 64 + i], wp, acc[j]);
    }
    #pragma unroll
    for (int j = 0; j < 4; ++j)
        g_S[((size_t)(bq * 4 + j) * 64 + o) * 1024 + m] = acc[j];
}

// ---------------------------------------------------------------------------
// Inverse: per (b,o) block, 32x32 modes -> 256x256 real + bias
// smem: ci[32][130] f2 (c,s) | t4i[256] f4 (c,s,-s,c) | S[32][32] u64 | G[16][32] u64
// ---------------------------------------------------------------------------
#define INV_SMEM_BYTES (32*130*8 + 256*16 + 32*32*8 + 16*32*8)

__global__ __launch_bounds__(256) void inv_kernel(const float* __restrict__ bias,
                                                  float* __restrict__ out) {
    extern __shared__ char smraw[];
    float2* s_ci  = (float2*)smraw;                 // [kk*130 + w]
    float4* s_t4i = (float4*)(s_ci + 32 * 130);     // [n] = (c, s, -s, c)
    u64*    s_S   = (u64*)(s_t4i + 256);            // [ky*32 + kx], pre-scaled
    u64*    s_G   = s_S + 32 * 32;                  // [r*32 + kk]

    const int t  = threadIdx.x;
    const int bo = blockIdx.x;
    const int o  = bo & 63;

    for (int idx = t; idx < 32 * 129; idx += 256) {
        int kk = idx / 129;
        int w  = idx - kk * 129;
        float sv, cv;
        sincospif(((kk * w) & 255) * (2.0f / 256.0f), &sv, &cv);
        s_ci[kk * 130 + w] = make_float2(cv, sv);
    }
    {
        int n = t;
        float sv, cv;
        sincospif(n * (2.0f / 256.0f), &sv, &cv);
        s_t4i[n] = make_float4(cv, sv, -sv, cv);
    }
    for (int e = t; e < 1024; e += 256) {
        float2 v  = u2f(g_S[(size_t)bo * 1024 + e]);
        float sc  = ((e & 31) == 0 ? 1.f : 2.f) * (1.f / 65536.f);
        s_S[e] = f2u(v.x * sc, v.y * sc);
    }
    const float bias_o = bias[o];
    __syncthreads();

    // C1 mapping: lanes over kx, warp -> row pair
    const int kx = t & 31, r2 = t >> 5;
    // C2 mapping: warp tile = 16 w x 16 rows; thread 2 w x 4 rows
    const int warp = t >> 5, lane = t & 31;
    const int wl = lane & 7, rl = lane >> 3;
    const int w0 = warp * 16 + wl * 2;           // even, 0..126

    const u64* ci64 = (const u64*)s_ci;
    float* yp = out + (size_t)bo * (Hn * Wn);

    for (int c = 0; c < 16; ++c) {
        const int hb = c * 16;

        // ---- C1: G[h,kx] = sum_ky S * e^{+2 pi i ky h/256}
        {
            const int h1 = hb + r2, h2 = h1 + 8;
            u64 a1 = 0ull, a2 = 0ull;
            #pragma unroll 8
            for (int ky = 0; ky < 32; ++ky) {
                float2 sv = u2f(s_S[ky * 32 + kx]);
                u64 sxx = f2u(sv.x, sv.x);
                u64 syy = f2u(sv.y, sv.y);
                u64x2 e1 = *(const u64x2*)&s_t4i[(ky * h1) & 255];
                u64x2 e2 = *(const u64x2*)&s_t4i[(ky * h2) & 255];
                a1 = ffma2(sxx, e1.x, a1);
                a1 = ffma2(syy, e1.y, a1);
                a2 = ffma2(sxx, e2.x, a2);
                a2 = ffma2(syy, e2.y, a2);
            }
            s_G[r2 * 32 + kx]       = a1;
            s_G[(r2 + 8) * 32 + kx] = a2;
        }
        __syncthreads();

        // ---- C2: y over (16 rows x cols w0,w0+1 and mirrors)
        {
            u64 acc[4][2];
            float aN[4];
            #pragma unroll
            for (int u = 0; u < 4; ++u) {
                acc[u][0] = acc[u][1] = 0ull; aN[u] = 0.f;
            }
            #pragma unroll 4
            for (int kk = 0; kk < 32; kk += 2) {
                u64x2 cs0 = *(const u64x2*)&ci64[kk * 130 + w0];        // (c,s) @ (kk, w0/w0+1)
                u64x2 cs1 = *(const u64x2*)&ci64[(kk + 1) * 130 + w0];
                #pragma unroll
                for (int u = 0; u < 4; ++u) {
                    u64x2 gv = *(const u64x2*)&s_G[(u * 4 + rl) * 32 + kk];
                    acc[u][0] = ffma2(gv.x, cs0.x, acc[u][0]);
                    acc[u][0] = ffma2(gv.y, cs1.x, acc[u][0]);
                    acc[u][1] = ffma2(gv.x, cs0.y, acc[u][1]);
                    acc[u][1] = ffma2(gv.y, cs1.y, acc[u][1]);
                    if (w0 == 0) {
                        aN[u] += u2f(gv.x).x - u2f(gv.y).x;
                    }
                }
            }
            #pragma unroll
            for (int u = 0; u < 4; ++u) {
                const int h = hb + u * 4 + rl;
                float2 a0 = u2f(acc[u][0]);   // (Sum gR c, Sum gI s) @ w0
                float2 a1 = u2f(acc[u][1]);   // @ w0+1
                float y00 = a0.x - a0.y + bias_o;   // col w0
                float y01 = a1.x - a1.y + bias_o;   // col w0+1
                float y10 = a0.x + a0.y + bias_o;   // col 256-w0
                float y11 = a1.x + a1.y + bias_o;   // col 255-w0
                *(float2*)&yp[h * 256 + w0] = make_float2(y00, y01);
                if (w0 == 0) {
                    yp[h * 256 + 255] = y11;
                    yp[h * 256 + 128] = aN[u] + bias_o;
                } else {
                    yp[h * 256 + (255 - w0)] = y11;
                    yp[h * 256 + (256 - w0)] = y10;
                }
            }
        }
        __syncthreads();
    }
}

// ---------------------------------------------------------------------------
extern "C" void kernel_launch(void* const* d_in, const int* in_sizes, int n_in,
                              void* d_out, int out_size) {
    const float* x    = (const float*)d_in[0];
    const float* wts  = (const float*)d_in[1];
    const float* bias = (const float*)d_in[2];
    float* out = (float*)d_out;

    cudaFuncSetAttribute(fwd_kernel, cudaFuncAttributeMaxDynamicSharedMemorySize,
                         FWD_SMEM_BYTES);
    cudaFuncSetAttribute(inv_kernel, cudaFuncAttributeMaxDynamicSharedMemorySize,
                         INV_SMEM_BYTES);

    fwd_kernel<<<Bn * CIN, 256, FWD_SMEM_BYTES>>>(x);
    mix_kernel<<<1024, 256>>>(wts);
    inv_kernel<<<Bn * COUT, 256, INV_SMEM_BYTES>>>(bias, out);
}